// round 8
// baseline (speedup 1.0000x reference)
#include <cuda_runtime.h>

// Shapes fixed by the problem's setup_inputs.
#define B_     16
#define N_     1024
#define M_     1024
#define CIN_   7
#define C_     8
#define COUT_  16
#define TM_    64      // m-values per block: 32 lanes x 2 m
#define NG_    128     // n's per warp (N/8)
#define THREADS_ 256   // 8 warps
#define EPS_   1e-8f

typedef unsigned long long ull;

__device__ __forceinline__ float ex2f(float v) {
    float r; asm("ex2.approx.f32 %0, %1;" : "=f"(r) : "f"(v)); return r;
}
__device__ __forceinline__ ull pack2(float lo, float hi) {
    ull r; asm("mov.b64 %0, {%1, %2};" : "=l"(r) : "f"(lo), "f"(hi)); return r;
}
__device__ __forceinline__ void unpack2(ull v, float& lo, float& hi) {
    asm("mov.b64 {%0, %1}, %2;" : "=f"(lo), "=f"(hi) : "l"(v));
}
// Packed dual-FMA / dual-ADD (Blackwell f32x2).
__device__ __forceinline__ ull fma2(ull a, ull b, ull c) {
    ull d; asm("fma.rn.f32x2 %0, %1, %2, %3;" : "=l"(d) : "l"(a), "l"(b), "l"(c));
    return d;
}
__device__ __forceinline__ ull add2(ull a, ull b) {
    ull d; asm("add.rn.f32x2 %0, %1, %2;" : "=l"(d) : "l"(a), "l"(b));
    return d;
}

// Shared memory (static), with aliasing:
//   [0,      8192)  sxq:  512 ulonglong2 {x_2p,x_2p+1 | q_2p,q_2p+1}
//   [8192,  24576)  syA:  1024 ulonglong2  {1,y0 | y1,y2}
//   [24576, 40960)  syB:  1024 ulonglong2  {y3,y4 | y5,y6}
//   [0,     14336)  sacc: 7 warps x 32 lanes x 16 floats (ALIASES tile; post-loop)
//   [40960, 41536)  sw (128 floats) + sb (16 floats)
#define SMEM_BYTES (40960 + 576)

__global__ __launch_bounds__(THREADS_, 4)
void convdeepset_kernel(const float* __restrict__ x,     // [B, N]
                        const float* __restrict__ y,     // [B, N, CIN]
                        const float* __restrict__ t,     // [B, M]
                        const float* __restrict__ sigma, // [C]
                        const float* __restrict__ w,     // [COUT, C]
                        const float* __restrict__ bias,  // [COUT]
                        float* __restrict__ out)         // [B, M, COUT]
{
    __shared__ __align__(16) char smem_raw[SMEM_BYTES];
    ulonglong2* sxq  = (ulonglong2*)smem_raw;              // [512]
    ulonglong2* syA  = (ulonglong2*)(smem_raw + 8192);     // [1024]
    ulonglong2* syB  = (ulonglong2*)(smem_raw + 24576);    // [1024]
    float*      sacc = (float*)smem_raw;                   // aliased, post-loop
    float*      sw   = (float*)(smem_raw + 40960);
    float*      sb   = sw + COUT_ * C_;

    const int b    = blockIdx.y;
    const int m0   = blockIdx.x * TM_;
    const int tid  = threadIdx.x;
    const int g    = tid >> 5;        // warp = n-group (0..7)
    const int lane = tid & 31;
    const int mA   = m0 + lane;       // first m this thread owns
    const int mB   = m0 + 32 + lane;  // second m

    if (tid < COUT_ * C_)                sw[tid] = w[tid];
    if (tid >= 128 && tid < 128 + COUT_) sb[tid - 128] = bias[tid - 128];

    // Per-channel exponent coefficient, log2e folded: arg = k2*(x-t)^2
    const float LOG2E = 1.4426950408889634f;
    const float s0 = expf(sigma[0]);
    const float k20 = -(0.5f * LOG2E) / (s0 * s0);
    bool uniform = true;
#pragma unroll
    for (int c = 1; c < C_; c++) {
        float s = expf(sigma[c]);
        uniform &= ((-(0.5f * LOG2E) / (s * s)) == k20);
    }

    const float tmA = t[b * M_ + mA];
    const float tmB = t[b * M_ + mB];
    // k2*(x-t)^2 = (k2*x^2) + U*x + T
    const ull UUA = pack2(-2.0f * k20 * tmA, -2.0f * k20 * tmA);
    const ull TTA = pack2(k20 * tmA * tmA,   k20 * tmA * tmA);
    const ull UUB = pack2(-2.0f * k20 * tmB, -2.0f * k20 * tmB);
    const ull TTB = pack2(k20 * tmB * tmB,   k20 * tmB * tmB);

    const float* xb  = x + b * N_;
    const float* ybp = y + (size_t)b * N_ * CIN_;

    // ---- Cooperative tile load: each thread loads 4 n's ----
    {
        float* sxqF = (float*)sxq;
#pragma unroll
        for (int r = 0; r < 4; r++) {
            const int n = tid + r * THREADS_;
            const float xv = xb[n];
            const int p = n >> 1, hh = n & 1;
            sxqF[p * 4 + hh]     = xv;
            sxqF[p * 4 + 2 + hh] = k20 * xv * xv;
            const float* yp = ybp + (size_t)n * CIN_;
            float y0 = yp[0], y1 = yp[1], y2 = yp[2], y3 = yp[3];
            float y4 = yp[4], y5 = yp[5], y6 = yp[6];
            syA[n] = make_ulonglong2(pack2(1.0f, y0), pack2(y1, y2));
            syB[n] = make_ulonglong2(pack2(y3, y4), pack2(y5, y6));
        }
    }
    __syncthreads();

    // Accumulators: [m(2)][channel-pair(4)]
    ull aA0 = 0, aA1 = 0, aA2 = 0, aA3 = 0;
    ull aB0 = 0, aB1 = 0, aB2 = 0, aB3 = 0;

    const ulonglong2* xq = sxq + g * (NG_ / 2);
    const ulonglong2* yA = syA + g * NG_;
    const ulonglong2* yB = syB + g * NG_;

    if (uniform) {
#pragma unroll 2
        for (int jj = 0; jj < NG_ / 2; jj++) {
            ulonglong2 v = xq[jj];                    // {x0,x1 | q0,q1}
            ull argsA = add2(fma2(UUA, v.x, TTA), v.y);
            ull argsB = add2(fma2(UUB, v.x, TTB), v.y);
            float fA0, fA1, fB0, fB1;
            unpack2(argsA, fA0, fA1);
            unpack2(argsB, fB0, fB1);
            float eA0 = ex2f(fA0), eA1 = ex2f(fA1);
            float eB0 = ex2f(fB0), eB1 = ex2f(fB1);

            {   // n = 2jj
                ulonglong2 A = yA[2 * jj], Bv = yB[2 * jj];
                ull eeA = pack2(eA0, eA0), eeB = pack2(eB0, eB0);
                aA0 = fma2(A.x,  eeA, aA0);
                aA1 = fma2(A.y,  eeA, aA1);
                aA2 = fma2(Bv.x, eeA, aA2);
                aA3 = fma2(Bv.y, eeA, aA3);
                aB0 = fma2(A.x,  eeB, aB0);
                aB1 = fma2(A.y,  eeB, aB1);
                aB2 = fma2(Bv.x, eeB, aB2);
                aB3 = fma2(Bv.y, eeB, aB3);
            }
            {   // n = 2jj+1
                ulonglong2 A = yA[2 * jj + 1], Bv = yB[2 * jj + 1];
                ull eeA = pack2(eA1, eA1), eeB = pack2(eB1, eB1);
                aA0 = fma2(A.x,  eeA, aA0);
                aA1 = fma2(A.y,  eeA, aA1);
                aA2 = fma2(Bv.x, eeA, aA2);
                aA3 = fma2(Bv.y, eeA, aA3);
                aB0 = fma2(A.x,  eeB, aB0);
                aB1 = fma2(A.y,  eeB, aB1);
                aB2 = fma2(Bv.x, eeB, aB2);
                aB3 = fma2(Bv.y, eeB, aB3);
            }
        }
    } else {
        // General path (arbitrary sigma): per-channel exponent, both m's.
        float k2[C_];
#pragma unroll
        for (int c = 0; c < C_; c++) {
            float s = expf(sigma[c]);
            k2[c] = -(0.5f * LOG2E) / (s * s);
        }
        float accsA[C_], accsB[C_];
#pragma unroll
        for (int c = 0; c < C_; c++) { accsA[c] = 0.0f; accsB[c] = 0.0f; }
        const float* xqF = (const float*)xq;
        for (int j = 0; j < NG_; j++) {
            const int p = j >> 1, hh = j & 1;
            const float xv = xqF[p * 4 + hh];
            const float dA = xv - tmA, dA2 = dA * dA;
            const float dB = xv - tmB, dB2 = dB * dB;
            ulonglong2 ya = yA[j], yb = yB[j];
            float yv[C_];
            unpack2(ya.x, yv[0], yv[1]);
            unpack2(ya.y, yv[2], yv[3]);
            unpack2(yb.x, yv[4], yv[5]);
            unpack2(yb.y, yv[6], yv[7]);
#pragma unroll
            for (int c = 0; c < C_; c++) {
                accsA[c] = fmaf(yv[c], ex2f(k2[c] * dA2), accsA[c]);
                accsB[c] = fmaf(yv[c], ex2f(k2[c] * dB2), accsB[c]);
            }
        }
        aA0 = pack2(accsA[0], accsA[1]);
        aA1 = pack2(accsA[2], accsA[3]);
        aA2 = pack2(accsA[4], accsA[5]);
        aA3 = pack2(accsA[6], accsA[7]);
        aB0 = pack2(accsB[0], accsB[1]);
        aB1 = pack2(accsB[2], accsB[3]);
        aB2 = pack2(accsB[4], accsB[5]);
        aB3 = pack2(accsB[6], accsB[7]);
    }

    // ---- Reduce the 8 warp partials (sacc aliases the dead tile) ----
    __syncthreads();
    if (g > 0) {
        ulonglong2* d2 = (ulonglong2*)(sacc + ((g - 1) * 32 + lane) * 16);
        d2[0] = make_ulonglong2(aA0, aA1);
        d2[1] = make_ulonglong2(aA2, aA3);
        d2[2] = make_ulonglong2(aB0, aB1);
        d2[3] = make_ulonglong2(aB2, aB3);
    }
    __syncthreads();
    if (g == 0) {
#pragma unroll
        for (int p = 0; p < 7; p++) {
            const ulonglong2* s2 = (const ulonglong2*)(sacc + (p * 32 + lane) * 16);
            ulonglong2 r0 = s2[0], r1 = s2[1], r2 = s2[2], r3 = s2[3];
            aA0 = add2(aA0, r0.x);
            aA1 = add2(aA1, r0.y);
            aA2 = add2(aA2, r1.x);
            aA3 = add2(aA3, r1.y);
            aB0 = add2(aB0, r2.x);
            aB1 = add2(aB1, r2.y);
            aB2 = add2(aB2, r3.x);
            aB3 = add2(aB3, r3.y);
        }

        // Fused epilogue for both m's.
#pragma unroll
        for (int s = 0; s < 2; s++) {
            float a[C_];
            if (s == 0) {
                unpack2(aA0, a[0], a[1]); unpack2(aA1, a[2], a[3]);
                unpack2(aA2, a[4], a[5]); unpack2(aA3, a[6], a[7]);
            } else {
                unpack2(aB0, a[0], a[1]); unpack2(aB1, a[2], a[3]);
                unpack2(aB2, a[4], a[5]); unpack2(aB3, a[6], a[7]);
            }
            float density = a[0];
            float inv = 1.0f / (density + EPS_);
            float feats[C_];
            feats[0] = density;
#pragma unroll
            for (int c = 1; c < C_; c++) feats[c] = a[c] * inv;

            const int m = s ? mB : mA;
            float* op = out + ((size_t)(b * M_ + m)) * COUT_;
#pragma unroll
            for (int og = 0; og < 4; og++) {
                float rr[4];
#pragma unroll
                for (int k = 0; k < 4; k++) {
                    const int o = og * 4 + k;
                    float sv = sb[o];
#pragma unroll
                    for (int c = 0; c < C_; c++)
                        sv = fmaf(sw[o * C_ + c], feats[c], sv);
                    rr[k] = sv;
                }
                *(float4*)(op + og * 4) = make_float4(rr[0], rr[1], rr[2], rr[3]);
            }
        }
    }
}

extern "C" void kernel_launch(void* const* d_in, const int* in_sizes, int n_in,
                              void* d_out, int out_size) {
    (void)in_sizes; (void)n_in; (void)out_size;
    const float* x     = (const float*)d_in[0];
    const float* y     = (const float*)d_in[1];
    const float* t     = (const float*)d_in[2];
    const float* sigma = (const float*)d_in[3];
    const float* w     = (const float*)d_in[4];
    const float* bias  = (const float*)d_in[5];
    float* out = (float*)d_out;

    dim3 grid(M_ / TM_, B_);
    convdeepset_kernel<<<grid, THREADS_>>>(x, y, t, sigma, w, bias, out);
}